// round 15
// baseline (speedup 1.0000x reference)
#include <cuda_runtime.h>
#include <cuda_bf16.h>
#include <math.h>
#include <stdint.h>

// Problem constants
#define Bdim 8
#define Hdim 252
#define Wdim 192
#define Cdim 64
#define Edim 192
#define HHn  84
#define WWn  64
#define NB   (Bdim*HHn*WWn)        // 43008 3x3 blocks
#define NPIX (Bdim*Hdim*Wdim)      // 387072 pixels
#define NATT 486                   // K^4 * HEADS = 81*6
#define SCALE_F 0.17677669529663687f  // 32^-0.5

// Scratch (device globals; no runtime allocation allowed)
__device__ float g_attn[(size_t)NB * NATT];                    // softmaxed attention (~84 MB)
__device__ __nv_bfloat16 g_mid_hi[(size_t)NPIX * Edim];        // mid, bf16 hi (~149 MB)
__device__ __nv_bfloat16 g_mid_lo[(size_t)NPIX * Edim];        // mid, bf16 lo (~149 MB)
__device__ __nv_bfloat16 g_wt_hi[Edim * Edim];                 // out_w^T hi, [n][k]
__device__ __nv_bfloat16 g_wt_lo[Edim * Edim];                 // out_w^T lo, [n][k]
__device__ __nv_bfloat16 g_vt_hi[Edim * Cdim];                 // v_w^T hi, [e][c]
__device__ __nv_bfloat16 g_vt_lo[Edim * Cdim];                 // v_w^T lo, [e][c]

// ---------------------------------------------------------------------------
// helpers
// ---------------------------------------------------------------------------
__device__ __forceinline__ unsigned long long fma2(unsigned long long a,
                                                   unsigned long long b,
                                                   unsigned long long c) {
    unsigned long long d;
    asm("fma.rn.f32x2 %0, %1, %2, %3;" : "=l"(d) : "l"(a), "l"(b), "l"(c));
    return d;
}
__device__ __forceinline__ unsigned long long splat2(float v) {
    unsigned long long d;
    asm("mov.b64 %0, {%1, %1};" : "=l"(d) : "r"(__float_as_uint(v)));
    return d;
}
__device__ __forceinline__ float2 unpk2(unsigned long long v) {
    float2 r;
    asm("mov.b64 {%0, %1}, %2;" : "=f"(r.x), "=f"(r.y) : "l"(v));
    return r;
}
__device__ __forceinline__ uint32_t cvt_bf16x2(float hi, float lo) {
    uint32_t r;
    asm("cvt.rn.bf16x2.f32 %0, %1, %2;" : "=r"(r) : "f"(hi), "f"(lo));
    return r;
}
__device__ __forceinline__ uint32_t smem_u32(const void* p) {
    uint32_t a;
    asm("{ .reg .u64 t; cvta.to.shared.u64 t, %1; cvt.u32.u64 %0, t; }"
        : "=r"(a) : "l"(p));
    return a;
}
__device__ __forceinline__ void cpa16(uint32_t dst, const void* src) {
    asm volatile("cp.async.cg.shared.global [%0], [%1], 16;"
                 :: "r"(dst), "l"(src) : "memory");
}
__device__ __forceinline__ void ldsm_x4(uint32_t* rr, uint32_t addr) {
    asm volatile("ldmatrix.sync.aligned.m8n8.x4.shared.b16 {%0,%1,%2,%3}, [%4];"
        : "=r"(rr[0]), "=r"(rr[1]), "=r"(rr[2]), "=r"(rr[3]) : "r"(addr));
}
__device__ __forceinline__ void mma16816(float* c, const uint32_t* a,
                                         uint32_t b0, uint32_t b1) {
    asm("mma.sync.aligned.m16n8k16.row.col.f32.bf16.bf16.f32 "
        "{%0,%1,%2,%3}, {%4,%5,%6,%7}, {%8,%9}, {%0,%1,%2,%3};"
        : "+f"(c[0]), "+f"(c[1]), "+f"(c[2]), "+f"(c[3])
        : "r"(a[0]), "r"(a[1]), "r"(a[2]), "r"(a[3]), "r"(b0), "r"(b1));
}

// ---------------------------------------------------------------------------
// Kernel 0: split weights.  wt[n][k]=out_w[k][n]; vt[e][c]=v_w[c][e]
// ---------------------------------------------------------------------------
__global__ __launch_bounds__(256) void prep_kernel(const float* __restrict__ out_w,
                                                   const float* __restrict__ v_w)
{
    int idx = blockIdx.x * 256 + threadIdx.x;
    if (idx < Edim * Edim) {
        int n = idx / Edim, k = idx % Edim;
        float w = out_w[(size_t)k * Edim + n];
        __nv_bfloat16 h = __float2bfloat16(w);
        g_wt_hi[idx] = h;
        g_wt_lo[idx] = __float2bfloat16(w - __bfloat162float(h));
    }
    if (idx < Edim * Cdim) {
        int e = idx / Cdim, c = idx % Cdim;
        float w = v_w[(size_t)c * Edim + e];
        __nv_bfloat16 h = __float2bfloat16(w);
        g_vt_hi[idx] = h;
        g_vt_lo[idx] = __float2bfloat16(w - __bfloat162float(h));
    }
}

// ---------------------------------------------------------------------------
// Kernel 1: pooled mean + attn GEMM (+bias,*scale) + softmax.  f32x2 over m.
// ---------------------------------------------------------------------------
__global__ __launch_bounds__(512) void attn_kernel(
    const float* __restrict__ x,
    const float* __restrict__ attn_w,
    const float* __restrict__ attn_b)
{
    __shared__ float pooled_t[64][18];
    __shared__ float attn_s[16][NATT + 2];

    const int blk0 = blockIdx.x * 16;
    const int tid  = threadIdx.x;

    for (int idx = tid; idx < 16 * 64; idx += 512) {
        int ml = idx >> 6, c = idx & 63;
        int blk = blk0 + ml;
        int b   = blk / (HHn * WWn);
        int rem = blk % (HHn * WWn);
        int i   = rem / WWn;
        int j   = rem % WWn;
        const float* xp = x + ((size_t)((size_t)b * Hdim + 3 * i) * Wdim + 3 * j) * Cdim + c;
        float s = 0.f;
        #pragma unroll
        for (int r = 0; r < 3; r++)
            #pragma unroll
            for (int ss = 0; ss < 3; ss++)
                s += xp[((size_t)r * Wdim + ss) * Cdim];
        pooled_t[c][ml] = s * (1.f / 9.f);
    }
    __syncthreads();

    if (tid < NATT) {
        unsigned long long acc2[8];
        #pragma unroll
        for (int mp = 0; mp < 8; mp++) acc2[mp] = 0ull;
        #pragma unroll 4
        for (int c = 0; c < 64; c++) {
            unsigned long long wp = splat2(attn_w[c * NATT + tid]);
            #pragma unroll
            for (int mp = 0; mp < 8; mp++) {
                unsigned long long pp =
                    *(const unsigned long long*)&pooled_t[c][2 * mp];
                acc2[mp] = fma2(pp, wp, acc2[mp]);
            }
        }
        float bb = attn_b[tid];
        #pragma unroll
        for (int mp = 0; mp < 8; mp++) {
            float2 f = unpk2(acc2[mp]);
            attn_s[2 * mp + 0][tid] = (f.x + bb) * SCALE_F;
            attn_s[2 * mp + 1][tid] = (f.y + bb) * SCALE_F;
        }
    }
    __syncthreads();

    for (int t = tid; t < 16 * 54; t += 512) {
        int m = t / 54, g = t % 54;
        float* p = &attn_s[m][g * 9];
        float mx = p[0];
        #pragma unroll
        for (int q = 1; q < 9; q++) mx = fmaxf(mx, p[q]);
        float e[9];
        float s = 0.f;
        #pragma unroll
        for (int q = 0; q < 9; q++) { e[q] = __expf(p[q] - mx); s += e[q]; }
        float inv = 1.f / s;
        float* outp = &g_attn[(size_t)(blk0 + m) * NATT + g * 9];
        #pragma unroll
        for (int q = 0; q < 9; q++) outp[q] = e[q] * inv;
    }
}

// ---------------------------------------------------------------------------
// Kernel 2: FUSED  v = x@v_w (HMMA bf16-split)  +  o = attn@v (f32x2),
// storing mid bf16 hi/lo.  g_v eliminated entirely.
//
// CTA = 16 consecutive blocks of one (b,i) stripe = 144 pixels in [blk][p]
// row order.  M=144, N=192, K=64.  288 threads = 9 warps (warp tile 48x64).
// v accumulators -> smem (union with staging buffers), apply phase reads
// smem v + smem attn, writes g_mid directly.
// ---------------------------------------------------------------------------
#define VAROW 144                              // staging row: 128B data + 16 pad
#define FOFF_A_HI 0
#define FOFF_A_LO (144 * VAROW)                // 20736
#define FOFF_B_HI (2 * 144 * VAROW)            // 41472
#define FOFF_B_LO (FOFF_B_HI + 192 * VAROW)    // 69120
// v buffer overlaps A/B staging (valid: only written after MMA reads finish)
#define VSTRIDE 200                            // floats per v row (800B, 16B-mult)
#define FOFF_V 0
#define FOFF_ATT (144 * VSTRIDE * 4)           // 115200 (beyond staging's 96768)
#define FSM_TOTAL (FOFF_ATT + 16 * NATT * 4)   // 146304

__global__ __launch_bounds__(288) void vapply_kernel(const float* __restrict__ x)
{
    extern __shared__ char smem[];
    const uint32_t sb = smem_u32(smem);
    float* smf = (float*)smem;

    const int tid  = threadIdx.x;
    const int warp = tid >> 5;
    const int lane = tid & 31;
    const int quad = lane >> 3;
    const int r8   = lane & 7;
    const int warp_m = warp % 3;               // M block of 48
    const int warp_n = warp / 3;               // N block of 64

    // grid decode: 4 j-chunks x (84 i) x (8 b)
    const int bx = blockIdx.x;
    const int jc = bx & 3;
    const int st = bx >> 2;
    const int ii = st % HHn;
    const int bb = st / HHn;
    const int j0 = jc * 16;
    const int gblk0 = (bb * HHn + ii) * WWn + j0;    // first global block

    // ---- stage B (v_w^T hi/lo) via cp.async ----
    for (int idx = tid; idx < 1536; idx += 288) {
        int row = idx >> 3, q = idx & 7;
        int o = row * VAROW + q * 16;
        int s = row * 128 + q * 16;
        cpa16(sb + FOFF_B_HI + o, (const char*)g_vt_hi + s);
        cpa16(sb + FOFF_B_LO + o, (const char*)g_vt_lo + s);
    }
    asm volatile("cp.async.commit_group;" ::: "memory");

    // ---- stage attn (plain float2 copies; 8B-aligned source) ----
    {
        const float* asrc = &g_attn[(size_t)gblk0 * NATT];
        for (int idx = tid; idx < 3888; idx += 288) {
            *(float2*)&smf[FOFF_ATT / 4 + idx * 2] =
                *(const float2*)&asrc[idx * 2];
        }
    }

    // ---- stage A: x rows [l*9+p], bf16-split hi/lo ----
    #pragma unroll
    for (int it = 0; it < 8; it++) {
        int idx = it * 288 + tid;              // 0..2303
        int row = idx >> 4, c4 = idx & 15;
        int l = row / 9, p = row - l * 9;
        int r = p / 3, s = p - r * 3;
        const float* xp =
            &x[((size_t)((size_t)bb * Hdim + 3 * ii + r) * Wdim + 3 * (j0 + l) + s) * Cdim + c4 * 4];
        float4 f = *(const float4*)xp;
        uint32_t hi01 = cvt_bf16x2(f.y, f.x);
        uint32_t hi23 = cvt_bf16x2(f.w, f.z);
        float h0 = __uint_as_float(hi01 << 16);
        float h1 = __uint_as_float(hi01 & 0xFFFF0000u);
        float h2 = __uint_as_float(hi23 << 16);
        float h3 = __uint_as_float(hi23 & 0xFFFF0000u);
        uint32_t lo01 = cvt_bf16x2(f.y - h1, f.x - h0);
        uint32_t lo23 = cvt_bf16x2(f.w - h3, f.z - h2);
        int o = row * VAROW + c4 * 8;
        *(uint2*)(smem + FOFF_A_HI + o) = make_uint2(hi01, hi23);
        *(uint2*)(smem + FOFF_A_LO + o) = make_uint2(lo01, lo23);
    }
    asm volatile("cp.async.wait_group 0;" ::: "memory");
    __syncthreads();

    // ---- MMA: M=144 x N=192 x K=64 ----
    const int m_off = r8 + ((quad & 1) ? 8 : 0);
    const int akoff = (quad & 2) ? 16 : 0;
    const uint32_t aHi = sb + FOFF_A_HI + (warp_m * 48 + m_off) * VAROW + akoff;
    const int n_off = r8 + ((quad & 2) ? 8 : 0);
    const int bkoff = (quad & 1) ? 16 : 0;
    const uint32_t bAddr0 = sb + FOFF_B_HI + (warp_n * 64 + n_off) * VAROW + bkoff;

    float acc[3][8][4];
    #pragma unroll
    for (int mt = 0; mt < 3; mt++)
        #pragma unroll
        for (int nt = 0; nt < 8; nt++)
            #pragma unroll
            for (int q = 0; q < 4; q++) acc[mt][nt][q] = 0.f;

    #pragma unroll
    for (int ks = 0; ks < 4; ks++) {
        uint32_t ah[3][4], al[3][4];
        #pragma unroll
        for (int mt = 0; mt < 3; mt++) {
            ldsm_x4(ah[mt], aHi + mt * 16 * VAROW + ks * 32);
            ldsm_x4(al[mt], aHi + (FOFF_A_LO - FOFF_A_HI) + mt * 16 * VAROW + ks * 32);
        }
        #pragma unroll
        for (int ntp = 0; ntp < 4; ntp++) {
            uint32_t bh[4], bl[4];
            uint32_t ba = bAddr0 + ntp * 16 * VAROW + ks * 32;
            ldsm_x4(bh, ba);
            ldsm_x4(bl, ba + (FOFF_B_LO - FOFF_B_HI));
            #pragma unroll
            for (int mt = 0; mt < 3; mt++) {
                mma16816(acc[mt][2 * ntp],     ah[mt], bh[0], bh[1]);
                mma16816(acc[mt][2 * ntp],     al[mt], bh[0], bh[1]);
                mma16816(acc[mt][2 * ntp],     ah[mt], bl[0], bl[1]);
                mma16816(acc[mt][2 * ntp + 1], ah[mt], bh[2], bh[3]);
                mma16816(acc[mt][2 * ntp + 1], al[mt], bh[2], bh[3]);
                mma16816(acc[mt][2 * ntp + 1], ah[mt], bl[2], bl[3]);
            }
        }
    }
    __syncthreads();   // all staging reads done -> safe to overwrite with v

    // ---- write v fragments to smem ----
    {
        const int g = lane >> 2, t4 = lane & 3;
        #pragma unroll
        for (int nt = 0; nt < 8; nt++) {
            int col = warp_n * 64 + nt * 8 + 2 * t4;
            #pragma unroll
            for (int mt = 0; mt < 3; mt++) {
                int row = warp_m * 48 + mt * 16 + g;
                *(float2*)&smf[FOFF_V / 4 + row * VSTRIDE + col] =
                    make_float2(acc[mt][nt][0], acc[mt][nt][1]);
                *(float2*)&smf[FOFF_V / 4 + (row + 8) * VSTRIDE + col] =
                    make_float2(acc[mt][nt][2], acc[mt][nt][3]);
            }
        }
    }
    __syncthreads();

    // ---- apply: o = attn @ v, store mid bf16 hi/lo ----
    for (int w = tid; w < 768; w += 288) {
        int l  = w / 48;
        int ep = w - l * 48;
        int e0 = ep * 4;
        int h  = ep >> 3;

        unsigned long long vq[9][2];
        #pragma unroll
        for (int q = 0; q < 9; q++) {
            const float* vp = &smf[FOFF_V / 4 + (l * 9 + q) * VSTRIDE + e0];
            ulonglong2 u = *(const ulonglong2*)vp;
            vq[q][0] = u.x;
            vq[q][1] = u.y;
        }

        const float* ap_base = &smf[FOFF_ATT / 4 + l * NATT + h * 81];
        const size_t pixbase =
            ((size_t)bb * Hdim + 3 * ii) * Wdim + 3 * (j0 + l);
        __nv_bfloat16* hi_base = &g_mid_hi[pixbase * Edim + e0];
        __nv_bfloat16* lo_base = &g_mid_lo[pixbase * Edim + e0];

        #pragma unroll
        for (int p = 0; p < 9; p++) {
            const float* ap = ap_base + p * 9;
            unsigned long long a0 = 0ull, a1 = 0ull;
            #pragma unroll
            for (int q = 0; q < 9; q++) {
                unsigned long long av = splat2(ap[q]);
                a0 = fma2(av, vq[q][0], a0);
                a1 = fma2(av, vq[q][1], a1);
            }
            float2 f01 = unpk2(a0), f23 = unpk2(a1);
            uint32_t hi01 = cvt_bf16x2(f01.y, f01.x);
            uint32_t hi23 = cvt_bf16x2(f23.y, f23.x);
            float h0 = __uint_as_float(hi01 << 16);
            float h1 = __uint_as_float(hi01 & 0xFFFF0000u);
            float h2 = __uint_as_float(hi23 << 16);
            float h3 = __uint_as_float(hi23 & 0xFFFF0000u);
            uint32_t lo01 = cvt_bf16x2(f01.y - h1, f01.x - h0);
            uint32_t lo23 = cvt_bf16x2(f23.y - h3, f23.x - h2);
            const int off = ((p / 3) * Wdim + (p % 3)) * Edim;
            *(uint2*)(hi_base + off) = make_uint2(hi01, hi23);
            *(uint2*)(lo_base + off) = make_uint2(lo01, lo23);
        }
    }
}

// ---------------------------------------------------------------------------
// Kernel 3: projection via HMMA.  B resident; A double-buffered cp.async.
// CTA tile M=128 x N=192; 512 threads = 16 warps (warp 32x48, 4/SMSP).
// ---------------------------------------------------------------------------
#define BROW 400
#define AROW 144
#define OFF_B_HI 0
#define OFF_B_LO (192 * BROW)
#define OFF_A    (2 * 192 * BROW)
#define A_BUF_SZ (2 * 128 * AROW)
#define A_HL_SZ  (128 * AROW)
#define PSM_TOTAL (OFF_A + 2 * A_BUF_SZ)       // 227328

__global__ __launch_bounds__(512) void proj_hmma_kernel(
    const float* __restrict__ out_b,
    float* __restrict__ outp)
{
    extern __shared__ char smem[];
    const uint32_t sb = smem_u32(smem);

    const int tid    = threadIdx.x;
    const int warp   = tid >> 5;
    const int lane   = tid & 31;
    const int g      = lane >> 2;
    const int t      = lane & 3;
    const int quad   = lane >> 3;
    const int r8     = lane & 7;
    const int warp_m = warp & 3;
    const int warp_n = warp >> 2;

    const size_t m0 = (size_t)blockIdx.x * 128;
    const char* Ah = (const char*)(g_mid_hi + m0 * Edim);
    const char* Al = (const char*)(g_mid_lo + m0 * Edim);

    for (int idx = tid; idx < 4608; idx += 512) {
        int row = idx / 24, q = idx % 24;
        int o = row * BROW + q * 16;
        int s = row * 384 + q * 16;
        cpa16(sb + OFF_B_HI + o, (const char*)g_wt_hi + s);
        cpa16(sb + OFF_B_LO + o, (const char*)g_wt_lo + s);
    }
    #pragma unroll
    for (int it = 0; it < 2; it++) {
        int idx = it * 512 + tid;
        int row = idx >> 3, q = idx & 7;
        size_t src = (size_t)row * 384 + q * 16;
        uint32_t d = sb + OFF_A + row * AROW + q * 16;
        cpa16(d, Ah + src);
        cpa16(d + A_HL_SZ, Al + src);
    }
    asm volatile("cp.async.commit_group;" ::: "memory");
    asm volatile("cp.async.wait_group 0;" ::: "memory");
    __syncthreads();

    const int m_off = r8 + ((quad & 1) ? 8 : 0);
    const int akoff = (quad & 2) ? 16 : 0;
    const uint32_t aAddr0 = sb + OFF_A + (warp_m * 32 + m_off) * AROW + akoff;
    const int n_off = r8 + ((quad & 2) ? 8 : 0);
    const int bkoff = (quad & 1) ? 16 : 0;
    const uint32_t bAddr0 = sb + (warp_n * 48 + n_off) * BROW + bkoff;

    float acc[2][6][4];
    #pragma unroll
    for (int mt = 0; mt < 2; mt++)
        #pragma unroll
        for (int nt = 0; nt < 6; nt++)
            #pragma unroll
            for (int q = 0; q < 4; q++) acc[mt][nt][q] = 0.f;

    for (int ch = 0; ch < 3; ch++) {
        if (ch < 2) {
            uint32_t base = sb + OFF_A + ((ch + 1) & 1) * A_BUF_SZ;
            #pragma unroll
            for (int it = 0; it < 2; it++) {
                int idx = it * 512 + tid;
                int row = idx >> 3, q = idx & 7;
                size_t src = (size_t)row * 384 + (ch + 1) * 128 + q * 16;
                uint32_t d = base + row * AROW + q * 16;
                cpa16(d, Ah + src);
                cpa16(d + A_HL_SZ, Al + src);
            }
            asm volatile("cp.async.commit_group;" ::: "memory");
        }

        const uint32_t abuf = aAddr0 + (ch & 1) * A_BUF_SZ;
        const uint32_t bko  = ch * 128;

        #pragma unroll
        for (int ks = 0; ks < 4; ks++) {
            uint32_t ah[2][4], al[2][4];
            #pragma unroll
            for (int mt = 0; mt < 2; mt++) {
                ldsm_x4(ah[mt], abuf + mt * 16 * AROW + ks * 32);
                ldsm_x4(al[mt], abuf + A_HL_SZ + mt * 16 * AROW + ks * 32);
            }
            #pragma unroll
            for (int ntp = 0; ntp < 3; ntp++) {
                uint32_t bh[4], bl[4];
                uint32_t ba = bAddr0 + ntp * 16 * BROW + bko + ks * 32;
                ldsm_x4(bh, ba + OFF_B_HI);
                ldsm_x4(bl, ba + OFF_B_LO);
                #pragma unroll
                for (int mt = 0; mt < 2; mt++) {
                    mma16816(acc[mt][2 * ntp],     ah[mt], bh[0], bh[1]);
                    mma16816(acc[mt][2 * ntp],     al[mt], bh[0], bh[1]);
                    mma16816(acc[mt][2 * ntp],     ah[mt], bl[0], bl[1]);
                    mma16816(acc[mt][2 * ntp + 1], ah[mt], bh[2], bh[3]);
                    mma16816(acc[mt][2 * ntp + 1], al[mt], bh[2], bh[3]);
                    mma16816(acc[mt][2 * ntp + 1], ah[mt], bl[2], bl[3]);
                }
            }
        }

        if (ch < 2) {
            asm volatile("cp.async.wait_group 0;" ::: "memory");
            __syncthreads();
        }
    }

    #pragma unroll
    for (int nt = 0; nt < 6; nt++) {
        int col = warp_n * 48 + nt * 8 + 2 * t;
        float2 bb = *(const float2*)&out_b[col];
        #pragma unroll
        for (int mt = 0; mt < 2; mt++) {
            size_t row = m0 + warp_m * 32 + mt * 16 + g;
            float2 v0 = make_float2(acc[mt][nt][0] + bb.x, acc[mt][nt][1] + bb.y);
            float2 v1 = make_float2(acc[mt][nt][2] + bb.x, acc[mt][nt][3] + bb.y);
            *(float2*)&outp[row * Edim + col]       = v0;
            *(float2*)&outp[(row + 8) * Edim + col] = v1;
        }
    }
}

// ---------------------------------------------------------------------------
extern "C" void kernel_launch(void* const* d_in, const int* in_sizes, int n_in,
                              void* d_out, int out_size)
{
    const float* x      = (const float*)d_in[0];
    const float* v_w    = (const float*)d_in[1];
    const float* attn_w = (const float*)d_in[2];
    const float* attn_b = (const float*)d_in[3];
    const float* out_w  = (const float*)d_in[4];
    const float* out_b  = (const float*)d_in[5];
    float* outp = (float*)d_out;

    cudaFuncSetAttribute(vapply_kernel,
                         cudaFuncAttributeMaxDynamicSharedMemorySize, FSM_TOTAL);
    cudaFuncSetAttribute(proj_hmma_kernel,
                         cudaFuncAttributeMaxDynamicSharedMemorySize, PSM_TOTAL);

    prep_kernel<<<(Edim * Edim + 255) / 256, 256>>>(out_w, v_w);
    attn_kernel<<<NB / 16, 512>>>(x, attn_w, attn_b);
    vapply_kernel<<<Bdim * HHn * 4, 288, FSM_TOTAL>>>(x);
    proj_hmma_kernel<<<NPIX / 128, 512, PSM_TOTAL>>>(out_b, outp);
}

// round 16
// speedup vs baseline: 1.0140x; 1.0140x over previous
#include <cuda_runtime.h>
#include <cuda_bf16.h>
#include <math.h>
#include <stdint.h>

// Problem constants
#define Bdim 8
#define Hdim 252
#define Wdim 192
#define Cdim 64
#define Edim 192
#define HHn  84
#define WWn  64
#define NB   (Bdim*HHn*WWn)        // 43008 3x3 blocks
#define NPIX (Bdim*Hdim*Wdim)      // 387072 pixels
#define NATT 486                   // K^4 * HEADS = 81*6
#define SCALE_F 0.17677669529663687f  // 32^-0.5

// Scratch (device globals; no runtime allocation allowed)
__device__ float g_attn[(size_t)NB * NATT];                    // softmaxed attention (~84 MB)
__device__ float g_v[(size_t)NPIX * Edim];                     // v = x@v_w, fp32 (~297 MB)
__device__ __nv_bfloat16 g_mid_hi[(size_t)NPIX * Edim];        // mid, bf16 hi (~149 MB)
__device__ __nv_bfloat16 g_mid_lo[(size_t)NPIX * Edim];        // mid, bf16 lo (~149 MB)
__device__ __nv_bfloat16 g_wt_hi[Edim * Edim];                 // out_w^T hi, [n][k]
__device__ __nv_bfloat16 g_wt_lo[Edim * Edim];                 // out_w^T lo, [n][k]
__device__ __nv_bfloat16 g_vt_hi[Edim * Cdim];                 // v_w^T hi, [e][c]
__device__ __nv_bfloat16 g_vt_lo[Edim * Cdim];                 // v_w^T lo, [e][c]

// ---------------------------------------------------------------------------
// helpers
// ---------------------------------------------------------------------------
__device__ __forceinline__ unsigned long long fma2(unsigned long long a,
                                                   unsigned long long b,
                                                   unsigned long long c) {
    unsigned long long d;
    asm("fma.rn.f32x2 %0, %1, %2, %3;" : "=l"(d) : "l"(a), "l"(b), "l"(c));
    return d;
}
__device__ __forceinline__ unsigned long long splat2(float v) {
    unsigned long long d;
    asm("mov.b64 %0, {%1, %1};" : "=l"(d) : "r"(__float_as_uint(v)));
    return d;
}
__device__ __forceinline__ float2 unpk2(unsigned long long v) {
    float2 r;
    asm("mov.b64 {%0, %1}, %2;" : "=f"(r.x), "=f"(r.y) : "l"(v));
    return r;
}
__device__ __forceinline__ uint32_t cvt_bf16x2(float hi, float lo) {
    uint32_t r;
    asm("cvt.rn.bf16x2.f32 %0, %1, %2;" : "=r"(r) : "f"(hi), "f"(lo));
    return r;
}
__device__ __forceinline__ uint32_t smem_u32(const void* p) {
    uint32_t a;
    asm("{ .reg .u64 t; cvta.to.shared.u64 t, %1; cvt.u32.u64 %0, t; }"
        : "=r"(a) : "l"(p));
    return a;
}
__device__ __forceinline__ void cpa16(uint32_t dst, const void* src) {
    asm volatile("cp.async.cg.shared.global [%0], [%1], 16;"
                 :: "r"(dst), "l"(src) : "memory");
}
__device__ __forceinline__ void ldsm_x4(uint32_t* rr, uint32_t addr) {
    asm volatile("ldmatrix.sync.aligned.m8n8.x4.shared.b16 {%0,%1,%2,%3}, [%4];"
        : "=r"(rr[0]), "=r"(rr[1]), "=r"(rr[2]), "=r"(rr[3]) : "r"(addr));
}
__device__ __forceinline__ void mma16816(float* c, const uint32_t* a,
                                         uint32_t b0, uint32_t b1) {
    asm("mma.sync.aligned.m16n8k16.row.col.f32.bf16.bf16.f32 "
        "{%0,%1,%2,%3}, {%4,%5,%6,%7}, {%8,%9}, {%0,%1,%2,%3};"
        : "+f"(c[0]), "+f"(c[1]), "+f"(c[2]), "+f"(c[3])
        : "r"(a[0]), "r"(a[1]), "r"(a[2]), "r"(a[3]), "r"(b0), "r"(b1));
}

// ---------------------------------------------------------------------------
// Kernel 0: split weights.  wt[n][k]=out_w[k][n]; vt[e][c]=v_w[c][e]
// ---------------------------------------------------------------------------
__global__ __launch_bounds__(256) void prep_kernel(const float* __restrict__ out_w,
                                                   const float* __restrict__ v_w)
{
    int idx = blockIdx.x * 256 + threadIdx.x;
    if (idx < Edim * Edim) {
        int n = idx / Edim, k = idx % Edim;
        float w = out_w[(size_t)k * Edim + n];
        __nv_bfloat16 h = __float2bfloat16(w);
        g_wt_hi[idx] = h;
        g_wt_lo[idx] = __float2bfloat16(w - __bfloat162float(h));
    }
    if (idx < Edim * Cdim) {
        int e = idx / Cdim, c = idx % Cdim;
        float w = v_w[(size_t)c * Edim + e];
        __nv_bfloat16 h = __float2bfloat16(w);
        g_vt_hi[idx] = h;
        g_vt_lo[idx] = __float2bfloat16(w - __bfloat162float(h));
    }
}

// ---------------------------------------------------------------------------
// Kernel 1: pooled mean + attn GEMM (+bias,*scale) + softmax.  f32x2 over m.
// ---------------------------------------------------------------------------
__global__ __launch_bounds__(512) void attn_kernel(
    const float* __restrict__ x,
    const float* __restrict__ attn_w,
    const float* __restrict__ attn_b)
{
    __shared__ float pooled_t[64][18];
    __shared__ float attn_s[16][NATT + 2];

    const int blk0 = blockIdx.x * 16;
    const int tid  = threadIdx.x;

    for (int idx = tid; idx < 16 * 64; idx += 512) {
        int ml = idx >> 6, c = idx & 63;
        int blk = blk0 + ml;
        int b   = blk / (HHn * WWn);
        int rem = blk % (HHn * WWn);
        int i   = rem / WWn;
        int j   = rem % WWn;
        const float* xp = x + ((size_t)((size_t)b * Hdim + 3 * i) * Wdim + 3 * j) * Cdim + c;
        float s = 0.f;
        #pragma unroll
        for (int r = 0; r < 3; r++)
            #pragma unroll
            for (int ss = 0; ss < 3; ss++)
                s += xp[((size_t)r * Wdim + ss) * Cdim];
        pooled_t[c][ml] = s * (1.f / 9.f);
    }
    __syncthreads();

    if (tid < NATT) {
        unsigned long long acc2[8];
        #pragma unroll
        for (int mp = 0; mp < 8; mp++) acc2[mp] = 0ull;
        #pragma unroll 4
        for (int c = 0; c < 64; c++) {
            unsigned long long wp = splat2(attn_w[c * NATT + tid]);
            #pragma unroll
            for (int mp = 0; mp < 8; mp++) {
                unsigned long long pp =
                    *(const unsigned long long*)&pooled_t[c][2 * mp];
                acc2[mp] = fma2(pp, wp, acc2[mp]);
            }
        }
        float bb = attn_b[tid];
        #pragma unroll
        for (int mp = 0; mp < 8; mp++) {
            float2 f = unpk2(acc2[mp]);
            attn_s[2 * mp + 0][tid] = (f.x + bb) * SCALE_F;
            attn_s[2 * mp + 1][tid] = (f.y + bb) * SCALE_F;
        }
    }
    __syncthreads();

    for (int t = tid; t < 16 * 54; t += 512) {
        int m = t / 54, g = t % 54;
        float* p = &attn_s[m][g * 9];
        float mx = p[0];
        #pragma unroll
        for (int q = 1; q < 9; q++) mx = fmaxf(mx, p[q]);
        float e[9];
        float s = 0.f;
        #pragma unroll
        for (int q = 0; q < 9; q++) { e[q] = __expf(p[q] - mx); s += e[q]; }
        float inv = 1.f / s;
        float* outp = &g_attn[(size_t)(blk0 + m) * NATT + g * 9];
        #pragma unroll
        for (int q = 0; q < 9; q++) outp[q] = e[q] * inv;
    }
}

// ---------------------------------------------------------------------------
// Kernel 2: v = x @ v_w via HMMA bf16-split (x split on the fly).
// M=128 pixels, N=192 embed, K=64.  256 threads = 8 warps (warp 32x96).
// Combo-major MMA order: 12 independent accumulators between re-touches.
// ---------------------------------------------------------------------------
#define VAROW 144
#define VOFF_A_HI 0
#define VOFF_A_LO (128 * VAROW)
#define VOFF_B_HI (2 * 128 * VAROW)
#define VOFF_B_LO (VOFF_B_HI + 192 * VAROW)
#define VSM_TOTAL (VOFF_B_LO + 192 * VAROW)    // 92160

__global__ __launch_bounds__(256) void v_hmma_kernel(const float* __restrict__ x)
{
    extern __shared__ char smem[];
    const uint32_t sb = smem_u32(smem);

    const int tid    = threadIdx.x;
    const int warp   = tid >> 5;
    const int lane   = tid & 31;
    const int g      = lane >> 2;
    const int t      = lane & 3;
    const int quad   = lane >> 3;
    const int r8     = lane & 7;
    const int warp_m = warp & 3;
    const int warp_n = warp >> 2;

    const size_t m0 = (size_t)blockIdx.x * 128;

    for (int idx = tid; idx < 1536; idx += 256) {
        int row = idx >> 3, q = idx & 7;
        int o = row * VAROW + q * 16;
        int s = row * 128 + q * 16;
        cpa16(sb + VOFF_B_HI + o, (const char*)g_vt_hi + s);
        cpa16(sb + VOFF_B_LO + o, (const char*)g_vt_lo + s);
    }
    asm volatile("cp.async.commit_group;" ::: "memory");

    #pragma unroll
    for (int it = 0; it < 8; it++) {
        int idx = it * 256 + tid;
        int row = idx >> 4, c4 = idx & 15;
        float4 f = *(const float4*)&x[(m0 + row) * Cdim + c4 * 4];
        uint32_t hi01 = cvt_bf16x2(f.y, f.x);
        uint32_t hi23 = cvt_bf16x2(f.w, f.z);
        float h0 = __uint_as_float(hi01 << 16);
        float h1 = __uint_as_float(hi01 & 0xFFFF0000u);
        float h2 = __uint_as_float(hi23 << 16);
        float h3 = __uint_as_float(hi23 & 0xFFFF0000u);
        uint32_t lo01 = cvt_bf16x2(f.y - h1, f.x - h0);
        uint32_t lo23 = cvt_bf16x2(f.w - h3, f.z - h2);
        int o = row * VAROW + c4 * 8;
        *(uint2*)(smem + VOFF_A_HI + o) = make_uint2(hi01, hi23);
        *(uint2*)(smem + VOFF_A_LO + o) = make_uint2(lo01, lo23);
    }
    asm volatile("cp.async.wait_group 0;" ::: "memory");
    __syncthreads();

    const int m_off = r8 + ((quad & 1) ? 8 : 0);
    const int akoff = (quad & 2) ? 16 : 0;
    const uint32_t aHi = sb + VOFF_A_HI + (warp_m * 32 + m_off) * VAROW + akoff;
    const int n_off = r8 + ((quad & 2) ? 8 : 0);
    const int bkoff = (quad & 1) ? 16 : 0;
    const uint32_t bAddr0 = sb + (warp_n * 96 + n_off) * VAROW + bkoff;

    float acc[2][12][4];
    #pragma unroll
    for (int mt = 0; mt < 2; mt++)
        #pragma unroll
        for (int nt = 0; nt < 12; nt++)
            #pragma unroll
            for (int q = 0; q < 4; q++) acc[mt][nt][q] = 0.f;

    #pragma unroll
    for (int ks = 0; ks < 4; ks++) {
        uint32_t ah[2][4], al[2][4];
        #pragma unroll
        for (int mt = 0; mt < 2; mt++) {
            ldsm_x4(ah[mt], aHi + mt * 16 * VAROW + ks * 32);
            ldsm_x4(al[mt], aHi + (VOFF_A_LO - VOFF_A_HI) + mt * 16 * VAROW + ks * 32);
        }
        // process N in halves of 3 ntp; combo-major inside each half:
        // 12 independent accumulators between re-touches of the same acc.
        #pragma unroll
        for (int hf = 0; hf < 2; hf++) {
            uint32_t bh[3][4], bl[3][4];
            #pragma unroll
            for (int u = 0; u < 3; u++) {
                uint32_t ba = bAddr0 + (hf * 3 + u) * 16 * VAROW + ks * 32;
                ldsm_x4(bh[u], ba + VOFF_B_HI);
                ldsm_x4(bl[u], ba + VOFF_B_LO);
            }
            #pragma unroll
            for (int mt = 0; mt < 2; mt++)
                #pragma unroll
                for (int u = 0; u < 3; u++) {
                    int nt = (hf * 3 + u) * 2;
                    mma16816(acc[mt][nt],     ah[mt], bh[u][0], bh[u][1]);
                    mma16816(acc[mt][nt + 1], ah[mt], bh[u][2], bh[u][3]);
                }
            #pragma unroll
            for (int mt = 0; mt < 2; mt++)
                #pragma unroll
                for (int u = 0; u < 3; u++) {
                    int nt = (hf * 3 + u) * 2;
                    mma16816(acc[mt][nt],     al[mt], bh[u][0], bh[u][1]);
                    mma16816(acc[mt][nt + 1], al[mt], bh[u][2], bh[u][3]);
                }
            #pragma unroll
            for (int mt = 0; mt < 2; mt++)
                #pragma unroll
                for (int u = 0; u < 3; u++) {
                    int nt = (hf * 3 + u) * 2;
                    mma16816(acc[mt][nt],     ah[mt], bl[u][0], bl[u][1]);
                    mma16816(acc[mt][nt + 1], ah[mt], bl[u][2], bl[u][3]);
                }
        }
    }

    #pragma unroll
    for (int nt = 0; nt < 12; nt++) {
        int col = warp_n * 96 + nt * 8 + 2 * t;
        #pragma unroll
        for (int mt = 0; mt < 2; mt++) {
            size_t row = m0 + warp_m * 32 + mt * 16 + g;
            *(float2*)&g_v[row * Edim + col] =
                make_float2(acc[mt][nt][0], acc[mt][nt][1]);
            *(float2*)&g_v[(row + 8) * Edim + col] =
                make_float2(acc[mt][nt][2], acc[mt][nt][3]);
        }
    }
}

// ---------------------------------------------------------------------------
// Kernel 3: apply  o = attn @ v ; store mid bf16 hi/lo.
// 8 blocks per CTA, 384 threads; thread = (block, 4 embeds).
// ---------------------------------------------------------------------------
#define OVB 8
__global__ __launch_bounds__(384) void apply_kernel()
{
    __shared__ float saa[OVB][NATT * 2];     // splatted attn

    const int tid  = threadIdx.x;
    const int lb   = tid / 48;
    const int ep   = tid % 48;
    const int e0   = ep * 4;
    const int blk0 = blockIdx.x * OVB;

    #pragma unroll
    for (int l = 0; l < OVB; l++) {
        const float* ga = &g_attn[(size_t)(blk0 + l) * NATT];
        for (int t = tid; t < NATT; t += 384) {
            float a = ga[t];
            *(float2*)&saa[l][t * 2] = make_float2(a, a);
        }
    }

    const int blk = blk0 + lb;
    const int b   = blk / (HHn * WWn);
    const int rem = blk - b * (HHn * WWn);
    const int i   = rem >> 6;
    const int j   = rem & 63;
    const size_t pixbase = ((size_t)b * Hdim + 3 * i) * Wdim + 3 * j;

    unsigned long long vq[9][2];
    #pragma unroll
    for (int q = 0; q < 9; q++) {
        size_t pix = pixbase + (q / 3) * Wdim + (q % 3);
        ulonglong2 u = *(const ulonglong2*)&g_v[pix * Edim + e0];
        vq[q][0] = u.x;
        vq[q][1] = u.y;
    }
    __syncthreads();

    const int h = ep >> 3;
    const float* ap_base = &saa[lb][h * 81 * 2];
    __nv_bfloat16* hi_base = &g_mid_hi[pixbase * Edim + e0];
    __nv_bfloat16* lo_base = &g_mid_lo[pixbase * Edim + e0];

    #pragma unroll
    for (int p = 0; p < 9; p++) {
        const unsigned long long* ap =
            (const unsigned long long*)(ap_base + p * 18);
        unsigned long long a0 = 0ull, a1 = 0ull;
        #pragma unroll
        for (int q = 0; q < 9; q++) {
            unsigned long long av = ap[q];
            a0 = fma2(av, vq[q][0], a0);
            a1 = fma2(av, vq[q][1], a1);
        }
        float2 f01 = unpk2(a0), f23 = unpk2(a1);
        uint32_t hi01 = cvt_bf16x2(f01.y, f01.x);
        uint32_t hi23 = cvt_bf16x2(f23.y, f23.x);
        float h0 = __uint_as_float(hi01 << 16);
        float h1 = __uint_as_float(hi01 & 0xFFFF0000u);
        float h2 = __uint_as_float(hi23 << 16);
        float h3 = __uint_as_float(hi23 & 0xFFFF0000u);
        uint32_t lo01 = cvt_bf16x2(f01.y - h1, f01.x - h0);
        uint32_t lo23 = cvt_bf16x2(f23.y - h3, f23.x - h2);
        const int off = ((p / 3) * Wdim + (p % 3)) * Edim;
        *(uint2*)(hi_base + off) = make_uint2(hi01, hi23);
        *(uint2*)(lo_base + off) = make_uint2(lo01, lo23);
    }
}

// ---------------------------------------------------------------------------
// Kernel 4: projection via HMMA.  B resident; A double-buffered cp.async.
// CTA tile M=128 x N=192; 512 threads = 16 warps (warp 32x48, 4/SMSP).
// Combo-major MMA order: 12 independent accumulators between re-touches.
// ---------------------------------------------------------------------------
#define BROW 400
#define AROW 144
#define OFF_B_HI 0
#define OFF_B_LO (192 * BROW)
#define OFF_A    (2 * 192 * BROW)
#define A_BUF_SZ (2 * 128 * AROW)
#define A_HL_SZ  (128 * AROW)
#define PSM_TOTAL (OFF_A + 2 * A_BUF_SZ)       // 227328

__global__ __launch_bounds__(512) void proj_hmma_kernel(
    const float* __restrict__ out_b,
    float* __restrict__ outp)
{
    extern __shared__ char smem[];
    const uint32_t sb = smem_u32(smem);

    const int tid    = threadIdx.x;
    const int warp   = tid >> 5;
    const int lane   = tid & 31;
    const int g      = lane >> 2;
    const int t      = lane & 3;
    const int quad   = lane >> 3;
    const int r8     = lane & 7;
    const int warp_m = warp & 3;
    const int warp_n = warp >> 2;

    const size_t m0 = (size_t)blockIdx.x * 128;
    const char* Ah = (const char*)(g_mid_hi + m0 * Edim);
    const char* Al = (const char*)(g_mid_lo + m0 * Edim);

    for (int idx = tid; idx < 4608; idx += 512) {
        int row = idx / 24, q = idx % 24;
        int o = row * BROW + q * 16;
        int s = row * 384 + q * 16;
        cpa16(sb + OFF_B_HI + o, (const char*)g_wt_hi + s);
        cpa16(sb + OFF_B_LO + o, (const char*)g_wt_lo + s);
    }
    #pragma unroll
    for (int it = 0; it < 2; it++) {
        int idx = it * 512 + tid;
        int row = idx >> 3, q = idx & 7;
        size_t src = (size_t)row * 384 + q * 16;
        uint32_t d = sb + OFF_A + row * AROW + q * 16;
        cpa16(d, Ah + src);
        cpa16(d + A_HL_SZ, Al + src);
    }
    asm volatile("cp.async.commit_group;" ::: "memory");
    asm volatile("cp.async.wait_group 0;" ::: "memory");
    __syncthreads();

    const int m_off = r8 + ((quad & 1) ? 8 : 0);
    const int akoff = (quad & 2) ? 16 : 0;
    const uint32_t aAddr0 = sb + OFF_A + (warp_m * 32 + m_off) * AROW + akoff;
    const int n_off = r8 + ((quad & 2) ? 8 : 0);
    const int bkoff = (quad & 1) ? 16 : 0;
    const uint32_t bAddr0 = sb + (warp_n * 48 + n_off) * BROW + bkoff;

    float acc[2][6][4];
    #pragma unroll
    for (int mt = 0; mt < 2; mt++)
        #pragma unroll
        for (int nt = 0; nt < 6; nt++)
            #pragma unroll
            for (int q = 0; q < 4; q++) acc[mt][nt][q] = 0.f;

    for (int ch = 0; ch < 3; ch++) {
        if (ch < 2) {
            uint32_t base = sb + OFF_A + ((ch + 1) & 1) * A_BUF_SZ;
            #pragma unroll
            for (int it = 0; it < 2; it++) {
                int idx = it * 512 + tid;
                int row = idx >> 3, q = idx & 7;
                size_t src = (size_t)row * 384 + (ch + 1) * 128 + q * 16;
                uint32_t d = base + row * AROW + q * 16;
                cpa16(d, Ah + src);
                cpa16(d + A_HL_SZ, Al + src);
            }
            asm volatile("cp.async.commit_group;" ::: "memory");
        }

        const uint32_t abuf = aAddr0 + (ch & 1) * A_BUF_SZ;
        const uint32_t bko  = ch * 128;

        #pragma unroll
        for (int ks = 0; ks < 4; ks++) {
            uint32_t ah[2][4], al[2][4], bh[3][4], bl[3][4];
            #pragma unroll
            for (int mt = 0; mt < 2; mt++) {
                ldsm_x4(ah[mt], abuf + mt * 16 * AROW + ks * 32);
                ldsm_x4(al[mt], abuf + A_HL_SZ + mt * 16 * AROW + ks * 32);
            }
            #pragma unroll
            for (int u = 0; u < 3; u++) {
                uint32_t ba = bAddr0 + u * 16 * BROW + bko + ks * 32;
                ldsm_x4(bh[u], ba + OFF_B_HI);
                ldsm_x4(bl[u], ba + OFF_B_LO);
            }
            // combo-major: 12 independent MMAs per combo
            #pragma unroll
            for (int mt = 0; mt < 2; mt++)
                #pragma unroll
                for (int u = 0; u < 3; u++) {
                    mma16816(acc[mt][2 * u],     ah[mt], bh[u][0], bh[u][1]);
                    mma16816(acc[mt][2 * u + 1], ah[mt], bh[u][2], bh[u][3]);
                }
            #pragma unroll
            for (int mt = 0; mt < 2; mt++)
                #pragma unroll
                for (int u = 0; u < 3; u++) {
                    mma16816(acc[mt][2 * u],     al[mt], bh[u][0], bh[u][1]);
                    mma16816(acc[mt][2 * u + 1], al[mt], bh[u][2], bh[u][3]);
                }
            #pragma unroll
            for (int mt = 0; mt < 2; mt++)
                #pragma unroll
                for (int u = 0; u < 3; u++) {
                    mma16816(acc[mt][2 * u],     ah[mt], bl[u][0], bl[u][1]);
                    mma16816(acc[mt][2 * u + 1], ah[mt], bl[u][2], bl[u][3]);
                }
        }

        if (ch < 2) {
            asm volatile("cp.async.wait_group 0;" ::: "memory");
            __syncthreads();
        }
    }

    #pragma unroll
    for (int nt = 0; nt < 6; nt++) {
        int col = warp_n * 48 + nt * 8 + 2 * t;
        float2 bb = *(const float2*)&out_b[col];
        #pragma unroll
        for (int mt = 0; mt < 2; mt++) {
            size_t row = m0 + warp_m * 32 + mt * 16 + g;
            float2 v0 = make_float2(acc[mt][nt][0] + bb.x, acc[mt][nt][1] + bb.y);
            float2 v1 = make_float2(acc[mt][nt][2] + bb.x, acc[mt][nt][3] + bb.y);
            *(float2*)&outp[row * Edim + col]       = v0;
            *(float2*)&outp[(row + 8) * Edim + col] = v1;
        }
    }
}

// ---------------------------------------------------------------------------
extern "C" void kernel_launch(void* const* d_in, const int* in_sizes, int n_in,
                              void* d_out, int out_size)
{
    const float* x      = (const float*)d_in[0];
    const float* v_w    = (const float*)d_in[1];
    const float* attn_w = (const float*)d_in[2];
    const float* attn_b = (const float*)d_in[3];
    const float* out_w  = (const float*)d_in[4];
    const float* out_b  = (const float*)d_in[5];
    float* outp = (float*)d_out;

    cudaFuncSetAttribute(v_hmma_kernel,
                         cudaFuncAttributeMaxDynamicSharedMemorySize, VSM_TOTAL);
    cudaFuncSetAttribute(proj_hmma_kernel,
                         cudaFuncAttributeMaxDynamicSharedMemorySize, PSM_TOTAL);

    prep_kernel<<<(Edim * Edim + 255) / 256, 256>>>(out_w, v_w);
    attn_kernel<<<NB / 16, 512>>>(x, attn_w, attn_b);
    v_hmma_kernel<<<NPIX / 128, 256, VSM_TOTAL>>>(x);
    apply_kernel<<<NB / OVB, 384>>>();
    proj_hmma_kernel<<<NPIX / 128, 512, PSM_TOTAL>>>(out_b, outp);
}

// round 17
// speedup vs baseline: 1.2449x; 1.2277x over previous
#include <cuda_runtime.h>
#include <cuda_bf16.h>
#include <cuda_fp16.h>
#include <math.h>
#include <stdint.h>

// Problem constants
#define Bdim 8
#define Hdim 252
#define Wdim 192
#define Cdim 64
#define Edim 192
#define HHn  84
#define WWn  64
#define NB   (Bdim*HHn*WWn)        // 43008 3x3 blocks
#define NPIX (Bdim*Hdim*Wdim)      // 387072 pixels
#define NATT 486                   // K^4 * HEADS = 81*6
#define SCALE_F 0.17677669529663687f  // 32^-0.5

// Scratch (device globals; no runtime allocation allowed)
__device__ float g_attn[(size_t)NB * NATT];                    // softmaxed attention (~84 MB)
__device__ float g_v[(size_t)NPIX * Edim];                     // v = x@v_w, fp32 (~297 MB)
__device__ __half g_mid[(size_t)NPIX * Edim];                  // mid, fp16 (~149 MB)
__device__ __half g_wt[Edim * Edim];                           // out_w^T fp16, [n][k]
__device__ __nv_bfloat16 g_vt_hi[Edim * Cdim];                 // v_w^T hi, [e][c]
__device__ __nv_bfloat16 g_vt_lo[Edim * Cdim];                 // v_w^T lo, [e][c]

// ---------------------------------------------------------------------------
// helpers
// ---------------------------------------------------------------------------
__device__ __forceinline__ unsigned long long fma2(unsigned long long a,
                                                   unsigned long long b,
                                                   unsigned long long c) {
    unsigned long long d;
    asm("fma.rn.f32x2 %0, %1, %2, %3;" : "=l"(d) : "l"(a), "l"(b), "l"(c));
    return d;
}
__device__ __forceinline__ unsigned long long splat2(float v) {
    unsigned long long d;
    asm("mov.b64 %0, {%1, %1};" : "=l"(d) : "r"(__float_as_uint(v)));
    return d;
}
__device__ __forceinline__ float2 unpk2(unsigned long long v) {
    float2 r;
    asm("mov.b64 {%0, %1}, %2;" : "=f"(r.x), "=f"(r.y) : "l"(v));
    return r;
}
__device__ __forceinline__ uint32_t cvt_bf16x2(float hi, float lo) {
    uint32_t r;
    asm("cvt.rn.bf16x2.f32 %0, %1, %2;" : "=r"(r) : "f"(hi), "f"(lo));
    return r;
}
__device__ __forceinline__ uint32_t smem_u32(const void* p) {
    uint32_t a;
    asm("{ .reg .u64 t; cvta.to.shared.u64 t, %1; cvt.u32.u64 %0, t; }"
        : "=r"(a) : "l"(p));
    return a;
}
__device__ __forceinline__ void cpa16(uint32_t dst, const void* src) {
    asm volatile("cp.async.cg.shared.global [%0], [%1], 16;"
                 :: "r"(dst), "l"(src) : "memory");
}
__device__ __forceinline__ void ldsm_x4(uint32_t* rr, uint32_t addr) {
    asm volatile("ldmatrix.sync.aligned.m8n8.x4.shared.b16 {%0,%1,%2,%3}, [%4];"
        : "=r"(rr[0]), "=r"(rr[1]), "=r"(rr[2]), "=r"(rr[3]) : "r"(addr));
}
__device__ __forceinline__ void mma16816(float* c, const uint32_t* a,
                                         uint32_t b0, uint32_t b1) {
    asm("mma.sync.aligned.m16n8k16.row.col.f32.bf16.bf16.f32 "
        "{%0,%1,%2,%3}, {%4,%5,%6,%7}, {%8,%9}, {%0,%1,%2,%3};"
        : "+f"(c[0]), "+f"(c[1]), "+f"(c[2]), "+f"(c[3])
        : "r"(a[0]), "r"(a[1]), "r"(a[2]), "r"(a[3]), "r"(b0), "r"(b1));
}
__device__ __forceinline__ void mma16816h(float* c, const uint32_t* a,
                                          uint32_t b0, uint32_t b1) {
    asm("mma.sync.aligned.m16n8k16.row.col.f32.f16.f16.f32 "
        "{%0,%1,%2,%3}, {%4,%5,%6,%7}, {%8,%9}, {%0,%1,%2,%3};"
        : "+f"(c[0]), "+f"(c[1]), "+f"(c[2]), "+f"(c[3])
        : "r"(a[0]), "r"(a[1]), "r"(a[2]), "r"(a[3]), "r"(b0), "r"(b1));
}

// ---------------------------------------------------------------------------
// Kernel 0: split/convert weights.  g_wt[n][k]=fp16(out_w[k][n]);
//           g_vt hi/lo [e][c] = bf16-split(v_w[c][e])
// ---------------------------------------------------------------------------
__global__ __launch_bounds__(256) void prep_kernel(const float* __restrict__ out_w,
                                                   const float* __restrict__ v_w)
{
    int idx = blockIdx.x * 256 + threadIdx.x;
    if (idx < Edim * Edim) {
        int n = idx / Edim, k = idx % Edim;
        g_wt[idx] = __float2half(out_w[(size_t)k * Edim + n]);
    }
    if (idx < Edim * Cdim) {
        int e = idx / Cdim, c = idx % Cdim;
        float w = v_w[(size_t)c * Edim + e];
        __nv_bfloat16 h = __float2bfloat16(w);
        g_vt_hi[idx] = h;
        g_vt_lo[idx] = __float2bfloat16(w - __bfloat162float(h));
    }
}

// ---------------------------------------------------------------------------
// Kernel 1: pooled mean + attn GEMM (+bias,*scale) + softmax.  f32x2 over m.
// ---------------------------------------------------------------------------
__global__ __launch_bounds__(512) void attn_kernel(
    const float* __restrict__ x,
    const float* __restrict__ attn_w,
    const float* __restrict__ attn_b)
{
    __shared__ float pooled_t[64][18];
    __shared__ float attn_s[16][NATT + 2];

    const int blk0 = blockIdx.x * 16;
    const int tid  = threadIdx.x;

    for (int idx = tid; idx < 16 * 64; idx += 512) {
        int ml = idx >> 6, c = idx & 63;
        int blk = blk0 + ml;
        int b   = blk / (HHn * WWn);
        int rem = blk % (HHn * WWn);
        int i   = rem / WWn;
        int j   = rem % WWn;
        const float* xp = x + ((size_t)((size_t)b * Hdim + 3 * i) * Wdim + 3 * j) * Cdim + c;
        float s = 0.f;
        #pragma unroll
        for (int r = 0; r < 3; r++)
            #pragma unroll
            for (int ss = 0; ss < 3; ss++)
                s += xp[((size_t)r * Wdim + ss) * Cdim];
        pooled_t[c][ml] = s * (1.f / 9.f);
    }
    __syncthreads();

    if (tid < NATT) {
        unsigned long long acc2[8];
        #pragma unroll
        for (int mp = 0; mp < 8; mp++) acc2[mp] = 0ull;
        #pragma unroll 4
        for (int c = 0; c < 64; c++) {
            unsigned long long wp = splat2(attn_w[c * NATT + tid]);
            #pragma unroll
            for (int mp = 0; mp < 8; mp++) {
                unsigned long long pp =
                    *(const unsigned long long*)&pooled_t[c][2 * mp];
                acc2[mp] = fma2(pp, wp, acc2[mp]);
            }
        }
        float bb = attn_b[tid];
        #pragma unroll
        for (int mp = 0; mp < 8; mp++) {
            float2 f = unpk2(acc2[mp]);
            attn_s[2 * mp + 0][tid] = (f.x + bb) * SCALE_F;
            attn_s[2 * mp + 1][tid] = (f.y + bb) * SCALE_F;
        }
    }
    __syncthreads();

    for (int t = tid; t < 16 * 54; t += 512) {
        int m = t / 54, g = t % 54;
        float* p = &attn_s[m][g * 9];
        float mx = p[0];
        #pragma unroll
        for (int q = 1; q < 9; q++) mx = fmaxf(mx, p[q]);
        float e[9];
        float s = 0.f;
        #pragma unroll
        for (int q = 0; q < 9; q++) { e[q] = __expf(p[q] - mx); s += e[q]; }
        float inv = 1.f / s;
        float* outp = &g_attn[(size_t)(blk0 + m) * NATT + g * 9];
        #pragma unroll
        for (int q = 0; q < 9; q++) outp[q] = e[q] * inv;
    }
}

// ---------------------------------------------------------------------------
// Kernel 2: v = x @ v_w via HMMA bf16-split (x split on the fly).  UNCHANGED.
// M=128 pixels, N=192 embed, K=64.  256 threads = 8 warps (warp 32x96).
// ---------------------------------------------------------------------------
#define VAROW 144
#define VOFF_A_HI 0
#define VOFF_A_LO (128 * VAROW)
#define VOFF_B_HI (2 * 128 * VAROW)
#define VOFF_B_LO (VOFF_B_HI + 192 * VAROW)
#define VSM_TOTAL (VOFF_B_LO + 192 * VAROW)    // 92160

__global__ __launch_bounds__(256) void v_hmma_kernel(const float* __restrict__ x)
{
    extern __shared__ char smem[];
    const uint32_t sb = smem_u32(smem);

    const int tid    = threadIdx.x;
    const int warp   = tid >> 5;
    const int lane   = tid & 31;
    const int g      = lane >> 2;
    const int t      = lane & 3;
    const int quad   = lane >> 3;
    const int r8     = lane & 7;
    const int warp_m = warp & 3;
    const int warp_n = warp >> 2;

    const size_t m0 = (size_t)blockIdx.x * 128;

    for (int idx = tid; idx < 1536; idx += 256) {
        int row = idx >> 3, q = idx & 7;
        int o = row * VAROW + q * 16;
        int s = row * 128 + q * 16;
        cpa16(sb + VOFF_B_HI + o, (const char*)g_vt_hi + s);
        cpa16(sb + VOFF_B_LO + o, (const char*)g_vt_lo + s);
    }
    asm volatile("cp.async.commit_group;" ::: "memory");

    #pragma unroll
    for (int it = 0; it < 8; it++) {
        int idx = it * 256 + tid;
        int row = idx >> 4, c4 = idx & 15;
        float4 f = *(const float4*)&x[(m0 + row) * Cdim + c4 * 4];
        uint32_t hi01 = cvt_bf16x2(f.y, f.x);
        uint32_t hi23 = cvt_bf16x2(f.w, f.z);
        float h0 = __uint_as_float(hi01 << 16);
        float h1 = __uint_as_float(hi01 & 0xFFFF0000u);
        float h2 = __uint_as_float(hi23 << 16);
        float h3 = __uint_as_float(hi23 & 0xFFFF0000u);
        uint32_t lo01 = cvt_bf16x2(f.y - h1, f.x - h0);
        uint32_t lo23 = cvt_bf16x2(f.w - h3, f.z - h2);
        int o = row * VAROW + c4 * 8;
        *(uint2*)(smem + VOFF_A_HI + o) = make_uint2(hi01, hi23);
        *(uint2*)(smem + VOFF_A_LO + o) = make_uint2(lo01, lo23);
    }
    asm volatile("cp.async.wait_group 0;" ::: "memory");
    __syncthreads();

    const int m_off = r8 + ((quad & 1) ? 8 : 0);
    const int akoff = (quad & 2) ? 16 : 0;
    const uint32_t aHi = sb + VOFF_A_HI + (warp_m * 32 + m_off) * VAROW + akoff;
    const int n_off = r8 + ((quad & 2) ? 8 : 0);
    const int bkoff = (quad & 1) ? 16 : 0;
    const uint32_t bAddr0 = sb + (warp_n * 96 + n_off) * VAROW + bkoff;

    float acc[2][12][4];
    #pragma unroll
    for (int mt = 0; mt < 2; mt++)
        #pragma unroll
        for (int nt = 0; nt < 12; nt++)
            #pragma unroll
            for (int q = 0; q < 4; q++) acc[mt][nt][q] = 0.f;

    #pragma unroll
    for (int ks = 0; ks < 4; ks++) {
        uint32_t ah[2][4], al[2][4];
        #pragma unroll
        for (int mt = 0; mt < 2; mt++) {
            ldsm_x4(ah[mt], aHi + mt * 16 * VAROW + ks * 32);
            ldsm_x4(al[mt], aHi + (VOFF_A_LO - VOFF_A_HI) + mt * 16 * VAROW + ks * 32);
        }
        #pragma unroll
        for (int hf = 0; hf < 2; hf++) {
            uint32_t bh[3][4], bl[3][4];
            #pragma unroll
            for (int u = 0; u < 3; u++) {
                uint32_t ba = bAddr0 + (hf * 3 + u) * 16 * VAROW + ks * 32;
                ldsm_x4(bh[u], ba + VOFF_B_HI);
                ldsm_x4(bl[u], ba + VOFF_B_LO);
            }
            #pragma unroll
            for (int mt = 0; mt < 2; mt++)
                #pragma unroll
                for (int u = 0; u < 3; u++) {
                    int nt = (hf * 3 + u) * 2;
                    mma16816(acc[mt][nt],     ah[mt], bh[u][0], bh[u][1]);
                    mma16816(acc[mt][nt + 1], ah[mt], bh[u][2], bh[u][3]);
                }
            #pragma unroll
            for (int mt = 0; mt < 2; mt++)
                #pragma unroll
                for (int u = 0; u < 3; u++) {
                    int nt = (hf * 3 + u) * 2;
                    mma16816(acc[mt][nt],     al[mt], bh[u][0], bh[u][1]);
                    mma16816(acc[mt][nt + 1], al[mt], bh[u][2], bh[u][3]);
                }
            #pragma unroll
            for (int mt = 0; mt < 2; mt++)
                #pragma unroll
                for (int u = 0; u < 3; u++) {
                    int nt = (hf * 3 + u) * 2;
                    mma16816(acc[mt][nt],     ah[mt], bl[u][0], bl[u][1]);
                    mma16816(acc[mt][nt + 1], ah[mt], bl[u][2], bl[u][3]);
                }
        }
    }

    #pragma unroll
    for (int nt = 0; nt < 12; nt++) {
        int col = warp_n * 96 + nt * 8 + 2 * t;
        #pragma unroll
        for (int mt = 0; mt < 2; mt++) {
            size_t row = m0 + warp_m * 32 + mt * 16 + g;
            *(float2*)&g_v[row * Edim + col] =
                make_float2(acc[mt][nt][0], acc[mt][nt][1]);
            *(float2*)&g_v[(row + 8) * Edim + col] =
                make_float2(acc[mt][nt][2], acc[mt][nt][3]);
        }
    }
}

// ---------------------------------------------------------------------------
// Kernel 3: apply  o = attn @ v ; store mid as SINGLE fp16.
// 8 blocks per CTA, 384 threads; thread = (block, 4 embeds).
// ---------------------------------------------------------------------------
#define OVB 8
__global__ __launch_bounds__(384) void apply_kernel()
{
    __shared__ float saa[OVB][NATT * 2];     // splatted attn

    const int tid  = threadIdx.x;
    const int lb   = tid / 48;
    const int ep   = tid % 48;
    const int e0   = ep * 4;
    const int blk0 = blockIdx.x * OVB;

    #pragma unroll
    for (int l = 0; l < OVB; l++) {
        const float* ga = &g_attn[(size_t)(blk0 + l) * NATT];
        for (int t = tid; t < NATT; t += 384) {
            float a = ga[t];
            *(float2*)&saa[l][t * 2] = make_float2(a, a);
        }
    }

    const int blk = blk0 + lb;
    const int b   = blk / (HHn * WWn);
    const int rem = blk - b * (HHn * WWn);
    const int i   = rem >> 6;
    const int j   = rem & 63;
    const size_t pixbase = ((size_t)b * Hdim + 3 * i) * Wdim + 3 * j;

    unsigned long long vq[9][2];
    #pragma unroll
    for (int q = 0; q < 9; q++) {
        size_t pix = pixbase + (q / 3) * Wdim + (q % 3);
        ulonglong2 u = *(const ulonglong2*)&g_v[pix * Edim + e0];
        vq[q][0] = u.x;
        vq[q][1] = u.y;
    }
    __syncthreads();

    const int h = ep >> 3;
    const float* ap_base = &saa[lb][h * 81 * 2];
    __half* mid_base = &g_mid[pixbase * Edim + e0];

    #pragma unroll
    for (int p = 0; p < 9; p++) {
        const unsigned long long* ap =
            (const unsigned long long*)(ap_base + p * 18);
        unsigned long long a0 = 0ull, a1 = 0ull;
        #pragma unroll
        for (int q = 0; q < 9; q++) {
            unsigned long long av = ap[q];
            a0 = fma2(av, vq[q][0], a0);
            a1 = fma2(av, vq[q][1], a1);
        }
        float2 f01 = unpk2(a0), f23 = unpk2(a1);
        __half2 h01 = __floats2half2_rn(f01.x, f01.y);
        __half2 h23 = __floats2half2_rn(f23.x, f23.y);
        const int off = ((p / 3) * Wdim + (p % 3)) * Edim;
        *(uint2*)(mid_base + off) =
            make_uint2(*(uint32_t*)&h01, *(uint32_t*)&h23);
    }
}

// ---------------------------------------------------------------------------
// Kernel 4: projection via SINGLE-fp16 HMMA.  B (out_w^T fp16, all K)
// resident; A chunks double-buffered cp.async.
// CTA tile M=128 x N=192; 512 threads = 16 warps (warp 32x48).
// smem 113664 -> 2 CTAs/SM.
// ---------------------------------------------------------------------------
#define BROW 400
#define AROW 144
#define OFF_B 0
#define OFF_A (192 * BROW)                     // 76800
#define A_BUF_SZ (128 * AROW)                  // 18432
#define PSM_TOTAL (OFF_A + 2 * A_BUF_SZ)       // 113664

__global__ __launch_bounds__(512) void proj_hmma_kernel(
    const float* __restrict__ out_b,
    float* __restrict__ outp)
{
    extern __shared__ char smem[];
    const uint32_t sb = smem_u32(smem);

    const int tid    = threadIdx.x;
    const int warp   = tid >> 5;
    const int lane   = tid & 31;
    const int g      = lane >> 2;
    const int t      = lane & 3;
    const int quad   = lane >> 3;
    const int r8     = lane & 7;
    const int warp_m = warp & 3;
    const int warp_n = warp >> 2;

    const size_t m0 = (size_t)blockIdx.x * 128;
    const char* Am = (const char*)(g_mid + m0 * Edim);

    // B resident (fp16 single) + A chunk 0
    for (int idx = tid; idx < 4608; idx += 512) {
        int row = idx / 24, q = idx % 24;
        cpa16(sb + OFF_B + row * BROW + q * 16, (const char*)g_wt + row * 384 + q * 16);
    }
    #pragma unroll
    for (int it = 0; it < 2; it++) {
        int idx = it * 512 + tid;
        int row = idx >> 3, q = idx & 7;
        cpa16(sb + OFF_A + row * AROW + q * 16,
              Am + (size_t)row * 384 + q * 16);
    }
    asm volatile("cp.async.commit_group;" ::: "memory");
    asm volatile("cp.async.wait_group 0;" ::: "memory");
    __syncthreads();

    const int m_off = r8 + ((quad & 1) ? 8 : 0);
    const int akoff = (quad & 2) ? 16 : 0;
    const uint32_t aAddr0 = sb + OFF_A + (warp_m * 32 + m_off) * AROW + akoff;
    const int n_off = r8 + ((quad & 2) ? 8 : 0);
    const int bkoff = (quad & 1) ? 16 : 0;
    const uint32_t bAddr0 = sb + OFF_B + (warp_n * 48 + n_off) * BROW + bkoff;

    float acc[2][6][4];
    #pragma unroll
    for (int mt = 0; mt < 2; mt++)
        #pragma unroll
        for (int nt = 0; nt < 6; nt++)
            #pragma unroll
            for (int q = 0; q < 4; q++) acc[mt][nt][q] = 0.f;

    for (int ch = 0; ch < 3; ch++) {
        if (ch < 2) {
            uint32_t base = sb + OFF_A + ((ch + 1) & 1) * A_BUF_SZ;
            #pragma unroll
            for (int it = 0; it < 2; it++) {
                int idx = it * 512 + tid;
                int row = idx >> 3, q = idx & 7;
                cpa16(base + row * AROW + q * 16,
                      Am + (size_t)row * 384 + (ch + 1) * 128 + q * 16);
            }
            asm volatile("cp.async.commit_group;" ::: "memory");
        }

        const uint32_t abuf = aAddr0 + (ch & 1) * A_BUF_SZ;
        const uint32_t bko  = ch * 128;

        #pragma unroll
        for (int ks = 0; ks < 4; ks++) {
            uint32_t ah[2][4], bh[3][4];
            #pragma unroll
            for (int mt = 0; mt < 2; mt++)
                ldsm_x4(ah[mt], abuf + mt * 16 * AROW + ks * 32);
            #pragma unroll
            for (int u = 0; u < 3; u++)
                ldsm_x4(bh[u], bAddr0 + u * 16 * BROW + bko + ks * 32);
            #pragma unroll
            for (int mt = 0; mt < 2; mt++)
                #pragma unroll
                for (int u = 0; u < 3; u++) {
                    mma16816h(acc[mt][2 * u],     ah[mt], bh[u][0], bh[u][1]);
                    mma16816h(acc[mt][2 * u + 1], ah[mt], bh[u][2], bh[u][3]);
                }
        }

        if (ch < 2) {
            asm volatile("cp.async.wait_group 0;" ::: "memory");
            __syncthreads();
        }
    }

    #pragma unroll
    for (int nt = 0; nt < 6; nt++) {
        int col = warp_n * 48 + nt * 8 + 2 * t;
        float2 bb = *(const float2*)&out_b[col];
        #pragma unroll
        for (int mt = 0; mt < 2; mt++) {
            size_t row = m0 + warp_m * 32 + mt * 16 + g;
            float2 v0 = make_float2(acc[mt][nt][0] + bb.x, acc[mt][nt][1] + bb.y);
            float2 v1 = make_float2(acc[mt][nt][2] + bb.x, acc[mt][nt][3] + bb.y);
            *(float2*)&outp[row * Edim + col]       = v0;
            *(float2*)&outp[(row + 8) * Edim + col] = v1;
        }
    }
}

// ---------------------------------------------------------------------------
extern "C" void kernel_launch(void* const* d_in, const int* in_sizes, int n_in,
                              void* d_out, int out_size)
{
    const float* x      = (const float*)d_in[0];
    const float* v_w    = (const float*)d_in[1];
    const float* attn_w = (const float*)d_in[2];
    const float* attn_b = (const float*)d_in[3];
    const float* out_w  = (const float*)d_in[4];
    const float* out_b  = (const float*)d_in[5];
    float* outp = (float*)d_out;

    cudaFuncSetAttribute(v_hmma_kernel,
                         cudaFuncAttributeMaxDynamicSharedMemorySize, VSM_TOTAL);
    cudaFuncSetAttribute(proj_hmma_kernel,
                         cudaFuncAttributeMaxDynamicSharedMemorySize, PSM_TOTAL);

    prep_kernel<<<(Edim * Edim + 255) / 256, 256>>>(out_w, v_w);
    attn_kernel<<<NB / 16, 512>>>(x, attn_w, attn_b);
    v_hmma_kernel<<<NPIX / 128, 256, VSM_TOTAL>>>(x);
    apply_kernel<<<NB / OVB, 384>>>();
    proj_hmma_kernel<<<NPIX / 128, 512, PSM_TOTAL>>>(out_b, outp);
}